// round 3
// baseline (speedup 1.0000x reference)
#include <cuda_runtime.h>
#include <math.h>

// Fused single-step GRU(hidden=1) + Linear(1,1).
// Input layout per row (65 fp32): [h0, x0..x63]. 524288 rows total.
//
// Strategy: 128 rows/block SMEM tile, coalesced float4 global loads
// (block slice = 128*65*4 B = 33280 B, 16B aligned), then thread-per-row
// compute from shared memory. Row pitch 65 -> (t+k) mod 32 bank pattern,
// conflict-free scalar LDS. Weights broadcast from smem as float4.

#define ROWS_PER_BLOCK 128
#define NTHREADS       128
#define FDIM           65
#define TILE_FLOATS    (ROWS_PER_BLOCK * FDIM)   // 8320
#define TILE_VEC4      (TILE_FLOATS / 4)         // 2080 (= 16*128 + 32)

__global__ void __launch_bounds__(NTHREADS, 1)
gru_fused_kernel(const float* __restrict__ in,
                 const float* __restrict__ Wih,   // [3,64] row-major = 192 floats
                 const float* __restrict__ Whh,   // [3,1]
                 const float* __restrict__ bih,   // [3]
                 const float* __restrict__ bhh,   // [3]
                 const float* __restrict__ wout,  // [1,1]
                 const float* __restrict__ bout,  // [1]
                 float* __restrict__ out,
                 int rows)
{
    __shared__ __align__(16) float smTile[TILE_FLOATS];
    __shared__ __align__(16) float smW[192];
    __shared__ float smP[11];   // Whh[3], bih[3], bhh[3], wout, bout

    const int tid = threadIdx.x;
    const int rowBase = blockIdx.x * ROWS_PER_BLOCK;
    if (rowBase >= rows) return;
    const bool fullTile = (rowBase + ROWS_PER_BLOCK) <= rows;

    // ---- cooperative tile load: fully coalesced, 16B-aligned float4 ----
    if (fullTile) {
        const float4* src = reinterpret_cast<const float4*>(
            in + (size_t)rowBase * FDIM);
        float4* dst = reinterpret_cast<float4*>(smTile);
        #pragma unroll
        for (int i = 0; i < 16; i++)
            dst[tid + i * NTHREADS] = src[tid + i * NTHREADS];
        if (tid < TILE_VEC4 - 16 * NTHREADS)          // remaining 32 vec4s
            dst[tid + 16 * NTHREADS] = src[tid + 16 * NTHREADS];
    } else {
        // tail tile (shape-variant safety; not hit for rows=524288)
        const int nflt = (rows - rowBase) * FDIM;
        const float* src = in + (size_t)rowBase * FDIM;
        for (int i = tid; i < nflt; i += NTHREADS) smTile[i] = src[i];
    }

    // ---- weights + scalars into smem ----
    if (tid < 48)
        reinterpret_cast<float4*>(smW)[tid] =
            reinterpret_cast<const float4*>(Wih)[tid];
    if (tid < 3) {
        smP[tid]     = Whh[tid];
        smP[3 + tid] = bih[tid];
        smP[6 + tid] = bhh[tid];
    }
    if (tid == 0) { smP[9] = wout[0]; smP[10] = bout[0]; }
    __syncthreads();

    const int myRow = rowBase + tid;
    if (myRow >= rows) return;

    // ---- thread t computes row t of this tile ----
    const float* row = smTile + tid * FDIM;
    const float h = row[0];

    // hoist scalar params into registers (single broadcast LDS each)
    const float whh_r = smP[0], whh_z = smP[1], whh_n = smP[2];
    const float bih_r = smP[3], bih_z = smP[4], bih_n = smP[5];
    const float bhh_r = smP[6], bhh_z = smP[7], bhh_n = smP[8];
    const float w_o   = smP[9], b_o   = smP[10];

    float s0 = 0.f, s1 = 0.f, s2 = 0.f;
    #pragma unroll
    for (int k = 0; k < 64; k += 4) {
        const float4 w0 = *reinterpret_cast<const float4*>(smW + k);
        const float4 w1 = *reinterpret_cast<const float4*>(smW + 64 + k);
        const float4 w2 = *reinterpret_cast<const float4*>(smW + 128 + k);
        const float x0 = row[1 + k];
        const float x1 = row[2 + k];
        const float x2 = row[3 + k];
        const float x3 = row[4 + k];
        s0 = fmaf(w0.x, x0, fmaf(w0.y, x1, fmaf(w0.z, x2, fmaf(w0.w, x3, s0))));
        s1 = fmaf(w1.x, x0, fmaf(w1.y, x1, fmaf(w1.z, x2, fmaf(w1.w, x3, s1))));
        s2 = fmaf(w2.x, x0, fmaf(w2.y, x1, fmaf(w2.z, x2, fmaf(w2.w, x3, s2))));
    }

    // gates (PyTorch order r, z, n)
    const float gr  = s0 + bih_r + fmaf(h, whh_r, bhh_r);
    const float gz  = s1 + bih_z + fmaf(h, whh_z, bhh_z);
    const float ghn = fmaf(h, whh_n, bhh_n);

    const float r = 1.f / (1.f + expf(-gr));
    const float z = 1.f / (1.f + expf(-gz));
    const float n = tanhf(s2 + bih_n + r * ghn);
    const float hn = fmaf(1.f - z, n, z * h);

    out[myRow] = fmaf(hn, w_o, b_o);
}

extern "C" void kernel_launch(void* const* d_in, const int* in_sizes, int n_in,
                              void* d_out, int out_size)
{
    const float* in   = (const float*)d_in[0];   // [B, N, 65]
    const float* Wih  = (const float*)d_in[1];   // [3, 64]
    const float* Whh  = (const float*)d_in[2];   // [3, 1]
    const float* bih  = (const float*)d_in[3];   // [3]
    const float* bhh  = (const float*)d_in[4];   // [3]
    const float* wout = (const float*)d_in[5];   // [1, 1]
    const float* bout = (const float*)d_in[6];   // [1]
    float* out = (float*)d_out;

    const int rows = out_size;                   // 524288
    const int blocks = (rows + ROWS_PER_BLOCK - 1) / ROWS_PER_BLOCK;

    gru_fused_kernel<<<blocks, NTHREADS>>>(in, Wih, Whh, bih, bhh,
                                           wout, bout, out, rows);
}

// round 6
// speedup vs baseline: 1.2108x; 1.2108x over previous
#include <cuda_runtime.h>
#include <math.h>
#include <stdint.h>

// Fused single-step GRU(hidden=1) + Linear(1,1).
// Input layout per row (65 fp32): [h0, x0..x63]. 524288 rows total.
//
// Persistent CTAs + cp.async (LDGSTS) double-buffered tile pipeline.
// While computing tile i from smem buffer A, the 33 KB prefetch of tile
// i+1 streams into buffer B — DRAM stays busy through the compute phase
// instead of alternating load/compute (R3 measured DRAM=53%).

#define ROWS_PER_BLOCK 128
#define NTHREADS       128
#define FDIM           65
#define TILE_FLOATS    (ROWS_PER_BLOCK * FDIM)   // 8320
#define TILE_VEC4      (TILE_FLOATS / 4)         // 2080 = 16*128 + 32

// dynamic smem layout: buf0 | buf1 | W(192) | P(12)
#define SMEM_FLOATS    (2 * TILE_FLOATS + 192 + 12)

__device__ __forceinline__ void cp_async16(uint32_t saddr, const void* gptr) {
    asm volatile("cp.async.cg.shared.global [%0], [%1], 16;\n"
                 :: "r"(saddr), "l"(gptr));
}
__device__ __forceinline__ void cp_async4(uint32_t saddr, const void* gptr) {
    asm volatile("cp.async.ca.shared.global [%0], [%1], 4;\n"
                 :: "r"(saddr), "l"(gptr));
}
__device__ __forceinline__ void cp_commit() {
    asm volatile("cp.async.commit_group;\n");
}
template <int N>
__device__ __forceinline__ void cp_wait() {
    asm volatile("cp.async.wait_group %0;\n" :: "n"(N));
}

__global__ void __launch_bounds__(NTHREADS, 1)
gru_fused_kernel(const float* __restrict__ in,
                 const float* __restrict__ Wih,   // [3,64]
                 const float* __restrict__ Whh,   // [3,1]
                 const float* __restrict__ bih,   // [3]
                 const float* __restrict__ bhh,   // [3]
                 const float* __restrict__ wout,  // [1,1]
                 const float* __restrict__ bout,  // [1]
                 float* __restrict__ out,
                 int rows, int nTiles)
{
    extern __shared__ __align__(16) float sm[];
    float* smW = sm + 2 * TILE_FLOATS;
    float* smP = smW + 192;

    const int tid = threadIdx.x;

    // ---- params into smem (once) ----
    if (tid < 48)
        reinterpret_cast<float4*>(smW)[tid] =
            reinterpret_cast<const float4*>(Wih)[tid];
    if (tid < 3) {
        smP[tid]     = Whh[tid];
        smP[3 + tid] = bih[tid];
        smP[6 + tid] = bhh[tid];
    }
    if (tid == 0) { smP[9] = wout[0]; smP[10] = bout[0]; }

    // ---- prefetch of one tile into buffer b ----
    auto prefetch = [&](int tile, int b) {
        float* buf = sm + b * TILE_FLOATS;
        const uint32_t sbase = (uint32_t)__cvta_generic_to_shared(buf);
        const float* src = in + (size_t)tile * TILE_FLOATS;
        if ((tile + 1) * ROWS_PER_BLOCK <= rows) {          // full tile
            #pragma unroll
            for (int i = 0; i < 16; i++)
                cp_async16(sbase + (uint32_t)(tid + i * NTHREADS) * 16u,
                           src + (tid + i * NTHREADS) * 4);
            if (tid < TILE_VEC4 - 16 * NTHREADS)            // last 32 vec4
                cp_async16(sbase + (uint32_t)(tid + 16 * NTHREADS) * 16u,
                           src + (tid + 16 * NTHREADS) * 4);
        } else {                                            // partial tail
            const int nflt = (rows - tile * ROWS_PER_BLOCK) * FDIM;
            for (int i = tid; i < nflt; i += NTHREADS)
                cp_async4(sbase + (uint32_t)i * 4u, src + i);
        }
    };

    const int t0 = (int)blockIdx.x;
    if (t0 < nTiles) prefetch(t0, 0);
    cp_commit();

    int bi = 0;
    for (int tile = t0; tile < nTiles; tile += gridDim.x) {
        const int nxt = tile + gridDim.x;
        if (nxt < nTiles) prefetch(nxt, bi ^ 1);
        cp_commit();            // empty group ok when no prefetch issued
        cp_wait<1>();           // current tile's group complete
        __syncthreads();        // tile data + (first iter) weights visible

        const float* row = sm + bi * TILE_FLOATS + tid * FDIM;
        const int myRow = tile * ROWS_PER_BLOCK + tid;
        if (myRow < rows) {
            const float h = row[0];
            const float whh_r = smP[0], whh_z = smP[1], whh_n = smP[2];
            const float bih_r = smP[3], bih_z = smP[4], bih_n = smP[5];
            const float bhh_r = smP[6], bhh_z = smP[7], bhh_n = smP[8];
            const float w_o   = smP[9], b_o   = smP[10];

            float s0 = 0.f, s1 = 0.f, s2 = 0.f;
            #pragma unroll
            for (int k = 0; k < 64; k += 4) {
                const float4 w0 = *reinterpret_cast<const float4*>(smW + k);
                const float4 w1 = *reinterpret_cast<const float4*>(smW + 64 + k);
                const float4 w2 = *reinterpret_cast<const float4*>(smW + 128 + k);
                const float x0 = row[1 + k];
                const float x1 = row[2 + k];
                const float x2 = row[3 + k];
                const float x3 = row[4 + k];
                s0 = fmaf(w0.x, x0, fmaf(w0.y, x1, fmaf(w0.z, x2, fmaf(w0.w, x3, s0))));
                s1 = fmaf(w1.x, x0, fmaf(w1.y, x1, fmaf(w1.z, x2, fmaf(w1.w, x3, s1))));
                s2 = fmaf(w2.x, x0, fmaf(w2.y, x1, fmaf(w2.z, x2, fmaf(w2.w, x3, s2))));
            }

            const float gr  = s0 + bih_r + fmaf(h, whh_r, bhh_r);
            const float gz  = s1 + bih_z + fmaf(h, whh_z, bhh_z);
            const float ghn = fmaf(h, whh_n, bhh_n);

            const float r = 1.f / (1.f + expf(-gr));
            const float z = 1.f / (1.f + expf(-gz));
            const float n = tanhf(s2 + bih_n + r * ghn);
            const float hn = fmaf(1.f - z, n, z * h);

            out[myRow] = fmaf(hn, w_o, b_o);
        }
        __syncthreads();        // everyone done reading buf bi before refill
        bi ^= 1;
    }
}

extern "C" void kernel_launch(void* const* d_in, const int* in_sizes, int n_in,
                              void* d_out, int out_size)
{
    const float* in   = (const float*)d_in[0];   // [B, N, 65]
    const float* Wih  = (const float*)d_in[1];   // [3, 64]
    const float* Whh  = (const float*)d_in[2];   // [3, 1]
    const float* bih  = (const float*)d_in[3];   // [3]
    const float* bhh  = (const float*)d_in[4];   // [3]
    const float* wout = (const float*)d_in[5];   // [1, 1]
    const float* bout = (const float*)d_in[6];   // [1]
    float* out = (float*)d_out;

    const int rows   = out_size;                 // 524288
    const int nTiles = (rows + ROWS_PER_BLOCK - 1) / ROWS_PER_BLOCK;  // 4096

    const int smemBytes = SMEM_FLOATS * (int)sizeof(float);           // ~67.4 KB
    cudaFuncSetAttribute(gru_fused_kernel,
                         cudaFuncAttributeMaxDynamicSharedMemorySize, smemBytes);

    // persistent grid: 3 CTAs/SM on 148 SMs (smem-limited: 3*67.4KB < 228KB)
    int grid = 444;
    if (grid > nTiles) grid = nTiles;

    gru_fused_kernel<<<grid, NTHREADS, smemBytes>>>(in, Wih, Whh, bih, bhh,
                                                    wout, bout, out,
                                                    rows, nTiles);
}

// round 7
// speedup vs baseline: 1.2297x; 1.0156x over previous
#include <cuda_runtime.h>
#include <math.h>
#include <stdint.h>

// Fused single-step GRU(hidden=1) + Linear(1,1).
// Input per row (65 fp32): [h0, x0..x63]. 524288 rows.
//
// R7: warp-autonomous double-buffered cp.async pipelines. Each warp owns a
// private 32-row smem tile pair and free-runs its own fetch/compute loop
// with __syncwarp only — no block barriers in steady state. R6 showed the
// lock-stepped block pipeline retired 100 KB/SM per ~5200-cyc iteration
// (DRAM 67%); decoupling warps shrinks the bubble per retired byte.

#define NTHREADS       128
#define NWARPS         4
#define WT_ROWS        32                        // rows per warp-tile
#define FDIM           65
#define WT_FLOATS      (WT_ROWS * FDIM)          // 2080
#define WT_VEC4        (WT_FLOATS / 4)           // 520 = 16*32 + 8
#define WT_BYTES       (WT_FLOATS * 4)           // 8320

// dynamic smem: 4 warps * 2 buffers * 2080 floats | W(192) | P(12)
#define SMEM_FLOATS    (NWARPS * 2 * WT_FLOATS + 192 + 12)

__device__ __forceinline__ void cp_async16(uint32_t saddr, const void* gptr) {
    asm volatile("cp.async.cg.shared.global [%0], [%1], 16;\n"
                 :: "r"(saddr), "l"(gptr));
}
__device__ __forceinline__ void cp_async4(uint32_t saddr, const void* gptr) {
    asm volatile("cp.async.ca.shared.global [%0], [%1], 4;\n"
                 :: "r"(saddr), "l"(gptr));
}
__device__ __forceinline__ void cp_commit() {
    asm volatile("cp.async.commit_group;\n");
}
template <int N>
__device__ __forceinline__ void cp_wait() {
    asm volatile("cp.async.wait_group %0;\n" :: "n"(N));
}

__global__ void __launch_bounds__(NTHREADS, 1)
gru_fused_kernel(const float* __restrict__ in,
                 const float* __restrict__ Wih,   // [3,64]
                 const float* __restrict__ Whh,   // [3,1]
                 const float* __restrict__ bih,   // [3]
                 const float* __restrict__ bhh,   // [3]
                 const float* __restrict__ wout,  // [1,1]
                 const float* __restrict__ bout,  // [1]
                 float* __restrict__ out,
                 int rows, int nWTiles)
{
    extern __shared__ __align__(16) float sm[];
    float* smW = sm + NWARPS * 2 * WT_FLOATS;
    float* smP = smW + 192;

    const int tid  = threadIdx.x;
    const int wid  = tid >> 5;
    const int lane = tid & 31;

    // ---- params into smem (once per CTA) ----
    if (tid < 48)
        reinterpret_cast<float4*>(smW)[tid] =
            reinterpret_cast<const float4*>(Wih)[tid];
    if (tid < 3) {
        smP[tid]     = Whh[tid];
        smP[3 + tid] = bih[tid];
        smP[6 + tid] = bhh[tid];
    }
    if (tid == 0) { smP[9] = wout[0]; smP[10] = bout[0]; }

    float* myBuf0 = sm + (wid * 2 + 0) * WT_FLOATS;
    float* myBuf1 = sm + (wid * 2 + 1) * WT_FLOATS;

    // ---- per-warp prefetch of one 32-row tile into buffer b ----
    auto prefetch = [&](int wt, int b) {
        float* buf = b ? myBuf1 : myBuf0;
        const uint32_t sbase = (uint32_t)__cvta_generic_to_shared(buf);
        const float* src = in + (size_t)wt * WT_FLOATS;
        if ((wt + 1) * WT_ROWS <= rows) {                  // full tile
            #pragma unroll
            for (int i = 0; i < 17; i++) {
                const int idx = lane + i * 32;
                if (idx < WT_VEC4)                          // last iter: lanes 0-7
                    cp_async16(sbase + (uint32_t)idx * 16u, src + idx * 4);
            }
        } else {                                            // partial tail
            const int nflt = (rows - wt * WT_ROWS) * FDIM;
            for (int i = lane; i < nflt; i += 32)
                cp_async4(sbase + (uint32_t)i * 4u, src + i);
        }
    };

    const int warpStride = (int)gridDim.x * NWARPS;
    const int w0 = (int)blockIdx.x * NWARPS + wid;

    if (w0 < nWTiles) prefetch(w0, 0);
    cp_commit();

    // single block barrier: weights/params visible to all warps
    __syncthreads();

    int bi = 0;
    for (int wt = w0; wt < nWTiles; wt += warpStride) {
        const int nxt = wt + warpStride;
        if (nxt < nWTiles) prefetch(nxt, bi ^ 1);
        cp_commit();            // empty group ok on last iteration
        cp_wait<1>();           // this warp's current tile complete
        __syncwarp();

        const float* row = (bi ? myBuf1 : myBuf0) + lane * FDIM;
        const int myRow = wt * WT_ROWS + lane;
        if (myRow < rows) {
            const float h = row[0];
            const float whh_r = smP[0], whh_z = smP[1], whh_n = smP[2];
            const float bih_r = smP[3], bih_z = smP[4], bih_n = smP[5];
            const float bhh_r = smP[6], bhh_z = smP[7], bhh_n = smP[8];
            const float w_o   = smP[9], b_o   = smP[10];

            float s0 = 0.f, s1 = 0.f, s2 = 0.f;
            #pragma unroll
            for (int k = 0; k < 64; k += 4) {
                const float4 w0v = *reinterpret_cast<const float4*>(smW + k);
                const float4 w1v = *reinterpret_cast<const float4*>(smW + 64 + k);
                const float4 w2v = *reinterpret_cast<const float4*>(smW + 128 + k);
                const float x0 = row[1 + k];
                const float x1 = row[2 + k];
                const float x2 = row[3 + k];
                const float x3 = row[4 + k];
                s0 = fmaf(w0v.x, x0, fmaf(w0v.y, x1, fmaf(w0v.z, x2, fmaf(w0v.w, x3, s0))));
                s1 = fmaf(w1v.x, x0, fmaf(w1v.y, x1, fmaf(w1v.z, x2, fmaf(w1v.w, x3, s1))));
                s2 = fmaf(w2v.x, x0, fmaf(w2v.y, x1, fmaf(w2v.z, x2, fmaf(w2v.w, x3, s2))));
            }

            const float gr  = s0 + bih_r + fmaf(h, whh_r, bhh_r);
            const float gz  = s1 + bih_z + fmaf(h, whh_z, bhh_z);
            const float ghn = fmaf(h, whh_n, bhh_n);

            const float r = 1.f / (1.f + expf(-gr));
            const float z = 1.f / (1.f + expf(-gz));
            const float n = tanhf(s2 + bih_n + r * ghn);
            const float hn = fmaf(1.f - z, n, z * h);

            out[myRow] = fmaf(hn, w_o, b_o);
        }
        __syncwarp();           // all lanes done reading before refill
        bi ^= 1;
    }
}

extern "C" void kernel_launch(void* const* d_in, const int* in_sizes, int n_in,
                              void* d_out, int out_size)
{
    const float* in   = (const float*)d_in[0];   // [B, N, 65]
    const float* Wih  = (const float*)d_in[1];   // [3, 64]
    const float* Whh  = (const float*)d_in[2];   // [3, 1]
    const float* bih  = (const float*)d_in[3];   // [3]
    const float* bhh  = (const float*)d_in[4];   // [3]
    const float* wout = (const float*)d_in[5];   // [1, 1]
    const float* bout = (const float*)d_in[6];   // [1]
    float* out = (float*)d_out;

    const int rows    = out_size;                // 524288
    const int nWTiles = (rows + WT_ROWS - 1) / WT_ROWS;   // 16384

    const int smemBytes = SMEM_FLOATS * (int)sizeof(float);   // ~67.3 KB
    cudaFuncSetAttribute(gru_fused_kernel,
                         cudaFuncAttributeMaxDynamicSharedMemorySize, smemBytes);

    // persistent grid: 3 CTAs/SM on 148 SMs (3*67.3KB < 228KB carveout)
    int grid = 444;
    const int maxGrid = (nWTiles + NWARPS - 1) / NWARPS;
    if (grid > maxGrid) grid = maxGrid;

    gru_fused_kernel<<<grid, NTHREADS, smemBytes>>>(in, Wih, Whh, bih, bhh,
                                                    wout, bout, out,
                                                    rows, nWTiles);
}